// round 1
// baseline (speedup 1.0000x reference)
#include <cuda_runtime.h>
#include <cstdint>

#define NB 32
#define NT 1024
#define ND 512
#define NU 512

// 64MB scratch for xw = x @ kernel   (static __device__ — no allocation)
__device__ float g_xw[NB * NT * NU];

// ---------------- f32x2 packed helpers ----------------
__device__ __forceinline__ unsigned long long pk2(float x) {
    unsigned long long r;
    asm("mov.b64 %0, {%1, %1};" : "=l"(r) : "f"(x));
    return r;
}
__device__ __forceinline__ unsigned long long pk2(float x, float y) {
    unsigned long long r;
    asm("mov.b64 %0, {%1, %2};" : "=l"(r) : "f"(x), "f"(y));
    return r;
}
__device__ __forceinline__ void fma2(unsigned long long& d, unsigned long long a,
                                     unsigned long long b) {
    asm("fma.rn.f32x2 %0, %1, %2, %0;" : "+l"(d) : "l"(a), "l"(b));
}
__device__ __forceinline__ float2 upk2(unsigned long long a) {
    float2 r;
    asm("mov.b64 {%0, %1}, %2;" : "=f"(r.x), "=f"(r.y) : "l"(a));
    return r;
}

// ======================================================================
// Kernel 1: XW = X[32768,512] @ W[512,512], fp32, f32x2-packed SIMT GEMM
// BM=128, BN=128, BK=8, 256 threads, 8x8 microtile
// ======================================================================
__global__ __launch_bounds__(256) void xw_gemm(const float* __restrict__ X,
                                               const float* __restrict__ W) {
    __shared__ float As[8][128];  // transposed: As[k][m]
    __shared__ float Bs[8][128];  // Bs[k][n]

    const int tid = threadIdx.x;
    const int m0 = blockIdx.y * 128;
    const int n0 = blockIdx.x * 128;

    const int ar = tid >> 1;           // 0..127 (m row within tile)
    const int ac = (tid & 1) * 4;      // 0 or 4 (k offset)
    const int br = tid >> 5;           // 0..7   (k row)
    const int bc = (tid & 31) * 4;     // 0..124 (n offset)

    const int tx = tid & 15;           // n frag = tx*8
    const int ty = tid >> 4;           // m frag = ty*8

    unsigned long long acc[8][4];
#pragma unroll
    for (int i = 0; i < 8; i++)
#pragma unroll
        for (int j = 0; j < 4; j++) acc[i][j] = 0ull;

    // prefetch tile 0
    float4 xa = *reinterpret_cast<const float4*>(&X[(size_t)(m0 + ar) * ND + ac]);
    float4 wb = *reinterpret_cast<const float4*>(&W[(size_t)br * NU + n0 + bc]);

    const int KT = ND / 8;  // 64
    for (int kt = 0; kt < KT; kt++) {
        // stage current tile into smem
        As[ac + 0][ar] = xa.x;
        As[ac + 1][ar] = xa.y;
        As[ac + 2][ar] = xa.z;
        As[ac + 3][ar] = xa.w;
        *reinterpret_cast<float4*>(&Bs[br][bc]) = wb;
        __syncthreads();

        // prefetch next tile (hidden under compute)
        if (kt + 1 < KT) {
            xa = *reinterpret_cast<const float4*>(
                &X[(size_t)(m0 + ar) * ND + (kt + 1) * 8 + ac]);
            wb = *reinterpret_cast<const float4*>(
                &W[(size_t)((kt + 1) * 8 + br) * NU + n0 + bc]);
        }

#pragma unroll
        for (int k = 0; k < 8; k++) {
            float4 a0 = *reinterpret_cast<const float4*>(&As[k][ty * 8]);
            float4 a1 = *reinterpret_cast<const float4*>(&As[k][ty * 8 + 4]);
            ulonglong2 bq0 = *reinterpret_cast<const ulonglong2*>(&Bs[k][tx * 8]);
            ulonglong2 bq1 = *reinterpret_cast<const ulonglong2*>(&Bs[k][tx * 8 + 4]);
            unsigned long long bb0 = bq0.x, bb1 = bq0.y, bb2 = bq1.x, bb3 = bq1.y;
            float av[8] = {a0.x, a0.y, a0.z, a0.w, a1.x, a1.y, a1.z, a1.w};
#pragma unroll
            for (int i = 0; i < 8; i++) {
                unsigned long long aa = pk2(av[i]);
                fma2(acc[i][0], aa, bb0);
                fma2(acc[i][1], aa, bb1);
                fma2(acc[i][2], aa, bb2);
                fma2(acc[i][3], aa, bb3);
            }
        }
        __syncthreads();
    }

    // epilogue
#pragma unroll
    for (int i = 0; i < 8; i++) {
        size_t row = (size_t)(m0 + ty * 8 + i);
        float2* op = reinterpret_cast<float2*>(&g_xw[row * NU + n0 + tx * 8]);
        op[0] = upk2(acc[i][0]);
        op[1] = upk2(acc[i][1]);
        op[2] = upk2(acc[i][2]);
        op[3] = upk2(acc[i][3]);
    }
}

// ======================================================================
// Kernel 2: sequential scan  h_t = xw_t + h_{t-1} @ R
// 16 clusters x 8 CTAs (128 SMs). Each cluster owns 2 batches; each CTA
// owns a 64-unit output slice with its R columns RESIDENT IN REGISTERS.
// Per step: packed-FMA partials -> smem reduce -> DSMEM push of the new
// h slice to all 8 cluster CTAs -> barrier.cluster.
// Thread layout: q = tid&15 selects a 4-unit quad; kb = tid>>4 selects a
// 32-wide k block (16-way k split, reduced through smem).
// ======================================================================
__global__ __launch_bounds__(256, 1) __cluster_dims__(8, 1, 1)
void scan_kernel(const float* __restrict__ R, float* __restrict__ out) {
    __shared__ float hbuf[2][2][NU];   // [parity][batch][k]  8KB
    __shared__ float red[256][8];      // per-thread partials  8KB

    const int tid = threadIdx.x;
    uint32_t rank;
    asm("mov.u32 %0, %%cluster_ctarank;" : "=r"(rank));
    const int cluster = blockIdx.x >> 3;
    const int b0 = cluster * 2;          // global batches b0, b0+1
    const int useg = (int)rank * 64;     // this CTA's unit slice

    const int q = tid & 15;              // u-quad index (16 quads = 64 units)
    const int kb = tid >> 4;             // k block (16 blocks of 32)
    const int ug = useg + q * 4;         // global base unit of quad
    const int k0 = kb * 32;

    // --- R slice into registers: u01[i]={R[k][ug],R[k][ug+1]}, u23: +2,+3 ---
    unsigned long long u01[32], u23[32];
#pragma unroll
    for (int i = 0; i < 32; i++) {
        float4 v = *reinterpret_cast<const float4*>(&R[(size_t)(k0 + i) * NU + ug]);
        u01[i] = pk2(v.x, v.y);
        u23[i] = pk2(v.z, v.w);
    }

    // zero h_0 (parity 0 buffer only)
    for (int i = tid; i < 2 * NU; i += 256) (&hbuf[0][0][0])[i] = 0.f;
    __syncthreads();
    asm volatile("barrier.cluster.arrive.aligned;" ::: "memory");
    asm volatile("barrier.cluster.wait.aligned;" ::: "memory");

    // --- owner threads (tid<128): one (batch, unit) output each ---
    const bool owner = tid < 128;
    const int ob = tid >> 6;             // 0/1 local batch
    const int ou = tid & 63;             // local unit
    const int oq = ou >> 2, oj = ou & 3;
    const float* xwp = &g_xw[((size_t)(b0 + ob) * NT) * NU + useg + ou];
    float* outp = &out[((size_t)(b0 + ob) * NT) * NU + useg + ou];
    float xw_cur = owner ? xwp[0] : 0.f;

    // precompute remote smem addresses of our h element in every cluster CTA
    uint32_t raddr[2][8];
    if (owner) {
#pragma unroll
        for (int par = 0; par < 2; par++) {
            uint32_t la = (uint32_t)__cvta_generic_to_shared(&hbuf[par][ob][useg + ou]);
#pragma unroll
            for (int d = 0; d < 8; d++) {
                asm("mapa.shared::cluster.u32 %0, %1, %2;"
                    : "=r"(raddr[par][d]) : "r"(la), "r"(d));
            }
        }
    }

    for (int t = 0; t < NT; t++) {
        const int cur = t & 1, nxt = cur ^ 1;

        // prefetch next xw early (hidden under FMA loop)
        float xw_nxt = 0.f;
        if (owner && (t + 1) < NT) xw_nxt = xwp[(size_t)(t + 1) * NU];

        // ---- partial matvec: acc[u-pair] over this thread's 32-k block ----
        const float* h0 = &hbuf[cur][0][k0];
        const float* h1 = &hbuf[cur][1][k0];
        unsigned long long a0p = 0, a0q = 0, a1p = 0, a1q = 0;
#pragma unroll
        for (int i4 = 0; i4 < 8; i4++) {
            float4 x0 = *reinterpret_cast<const float4*>(&h0[i4 * 4]);
            float4 x1 = *reinterpret_cast<const float4*>(&h1[i4 * 4]);
            unsigned long long hh;
            hh = pk2(x0.x); fma2(a0p, u01[i4 * 4 + 0], hh); fma2(a0q, u23[i4 * 4 + 0], hh);
            hh = pk2(x0.y); fma2(a0p, u01[i4 * 4 + 1], hh); fma2(a0q, u23[i4 * 4 + 1], hh);
            hh = pk2(x0.z); fma2(a0p, u01[i4 * 4 + 2], hh); fma2(a0q, u23[i4 * 4 + 2], hh);
            hh = pk2(x0.w); fma2(a0p, u01[i4 * 4 + 3], hh); fma2(a0q, u23[i4 * 4 + 3], hh);
            hh = pk2(x1.x); fma2(a1p, u01[i4 * 4 + 0], hh); fma2(a1q, u23[i4 * 4 + 0], hh);
            hh = pk2(x1.y); fma2(a1p, u01[i4 * 4 + 1], hh); fma2(a1q, u23[i4 * 4 + 1], hh);
            hh = pk2(x1.z); fma2(a1p, u01[i4 * 4 + 2], hh); fma2(a1q, u23[i4 * 4 + 2], hh);
            hh = pk2(x1.w); fma2(a1p, u01[i4 * 4 + 3], hh); fma2(a1q, u23[i4 * 4 + 3], hh);
        }

        // ---- stash partials (layout: red[kb*16+q][b*4+j]) ----
        {
            float2 p0 = upk2(a0p), p1 = upk2(a0q), p2 = upk2(a1p), p3 = upk2(a1q);
            float4* rp = reinterpret_cast<float4*>(&red[tid][0]);
            rp[0] = make_float4(p0.x, p0.y, p1.x, p1.y);
            rp[1] = make_float4(p2.x, p2.y, p3.x, p3.y);
        }
        __syncthreads();

        if (owner) {
            float s = 0.f;
#pragma unroll
            for (int r8 = 0; r8 < 16; r8++) s += red[r8 * 16 + oq][ob * 4 + oj];
            const float val = xw_cur + s;
            outp[(size_t)t * NU] = val;   // emit h_t
            // push new h element into every cluster CTA's next-parity buffer
#pragma unroll
            for (int d = 0; d < 8; d++) {
                asm volatile("st.shared::cluster.f32 [%0], %1;"
                             :: "r"(raddr[nxt][d]), "f"(val) : "memory");
            }
        }
        xw_cur = xw_nxt;

        // release our DSMEM stores / acquire everyone else's
        asm volatile("barrier.cluster.arrive.aligned;" ::: "memory");
        asm volatile("barrier.cluster.wait.aligned;" ::: "memory");
    }
}

// ======================================================================
extern "C" void kernel_launch(void* const* d_in, const int* in_sizes, int n_in,
                              void* d_out, int out_size) {
    const float* x = (const float*)d_in[0];            // [32,1024,512]
    const float* W = (const float*)d_in[1];            // kernel [512,512]
    const float* R = (const float*)d_in[2];            // recurrent_kernel [512,512]
    float* out = (float*)d_out;                        // [32,1024,512]

    dim3 gg(NU / 128, (NB * NT) / 128);                // (4, 256)
    xw_gemm<<<gg, 256>>>(x, W);
    scan_kernel<<<128, 256>>>(R, out);                 // 16 clusters x 8 CTAs
}